// round 12
// baseline (speedup 1.0000x reference)
#include <cuda_runtime.h>
#include <math_constants.h>

// Problem constants
#define GG      32
#define MAXB    16
#define MAXV    1024
#define MAXO    8192
#define NBX     64
#define NB2     (NBX * NBX)
#define XMIN2   (-4.0f)
#define W2      0.125f            // 8/64, exact power of two
#define INV2    8.0f
#define HWP     2                 // initial half-window, 5-NN phase (buckets)
#define EWP     2                 // expansion step
#define HWN     1                 // initial half-window, 1-NN phase
#define EWN     2
#define QTPB    256
#define BTPB    512
#define F_LOG2PI 1.8378770664093453f

// ---- scratch (static device globals: no allocation allowed) ----
__device__ float4 g_spts[MAXB * MAXO];     // (x,y)-bucketed {x,y,z,|p|^2}
__device__ float4 g_snrm[MAXB * MAXO];     // (x,y)-bucketed {nx,ny,nz,|n|^2}
__device__ int    g_nidx[MAXB * MAXO];     // original per-batch index of bucketed normal
__device__ int    g_op2[MAXB * (NB2 + 1)]; // exclusive offsets (points)
__device__ int    g_on2[MAXB * (NB2 + 1)]; // exclusive offsets (normals)
__device__ int    g_gid[MAXV];
__device__ float  g_chol[MAXB * GG * 10];
__device__ int    g_active[GG];
__device__ float  g_w[MAXB * MAXV];
__device__ float  g_sknn[MAXB * MAXV];
__device__ int    g_mnbits[MAXB * GG];
__device__ int    g_mxbits[MAXB * GG];
__device__ double g_dacc;
__device__ double g_pacc;

__device__ __forceinline__ int b2of(float x) {
    int bk = (int)floorf((x - XMIN2) * INV2);
    return bk < 0 ? 0 : (bk > NBX - 1 ? NBX - 1 : bk);
}

// Branchless sorted insert (ascending t0..t4 kept 5-smallest). 9 ops.
__device__ __forceinline__ void insert5(float a, float& t0, float& t1, float& t2,
                                        float& t3, float& t4) {
    float n0 = fminf(t0, a); a = fmaxf(t0, a);
    float n1 = fminf(t1, a); a = fmaxf(t1, a);
    float n2 = fminf(t2, a); a = fmaxf(t2, a);
    float n3 = fminf(t3, a); a = fmaxf(t3, a);
    float n4 = fminf(t4, a);
    t0 = n0; t1 = n1; t2 = n2; t3 = n3; t4 = n4;
}

// ---- kernel 1: gid; Cholesky; active; accumulator init ----
__global__ void init_kernel(const float* __restrict__ init_verts,
                            const float* __restrict__ init_anchors,
                            const float* __restrict__ contact_gaussians,
                            const float* __restrict__ anchor_verts,
                            int B, int V, int G) {
    int bi = blockIdx.x, tid = threadIdx.x;
    if (bi == 0) {
        for (int v = tid; v < V; v += 256) {
            float vx = init_verts[3*v], vy = init_verts[3*v+1], vz = init_verts[3*v+2];
            float best = CUDART_INF_F; int bg = 0;
            for (int g = 0; g < G; g++) {
                float dx = vx - init_anchors[3*g];
                float dy = vy - init_anchors[3*g+1];
                float dz = vz - init_anchors[3*g+2];
                float d2 = dx*dx + dy*dy + dz*dz;
                if (d2 < best) { best = d2; bg = g; }
            }
            g_gid[v] = bg;
        }
    } else {
        if (tid == 0) { g_dacc = 0.0; g_pacc = 0.0; }
        for (int i = tid; i < B * G; i += 256) {
            g_mnbits[i] = 0x7F800000;   // +inf
            g_mxbits[i] = 0;            // 0.0f acts as -inf (w >= 0)
        }
        for (int i = tid; i < B * G; i += 256) {
            const float* cg = contact_gaussians + (size_t)12 * i;
            float mx_ = cg[0] + anchor_verts[3*i+0];
            float my_ = cg[1] + anchor_verts[3*i+1];
            float mz_ = cg[2] + anchor_verts[3*i+2];
            float a00 = cg[3], a10 = cg[6], a11 = cg[7];
            float a20 = cg[9], a21 = cg[10], a22 = cg[11];
            float l00 = sqrtf(a00);
            float l10 = a10 / l00;
            float l20 = a20 / l00;
            float l11 = sqrtf(a11 - l10 * l10);
            float l21 = (a21 - l20 * l10) / l11;
            float l22 = sqrtf(a22 - l20 * l20 - l21 * l21);
            float hld = logf(l00) + logf(l11) + logf(l22);
            float* C = g_chol + 10 * i;
            C[0] = l10; C[1] = l20; C[2] = l21;
            C[3] = 1.0f / l00; C[4] = 1.0f / l11; C[5] = 1.0f / l22;
            C[6] = hld; C[7] = mx_; C[8] = my_; C[9] = mz_;
        }
        for (int g = tid; g < G; g += 256) {
            int act = 0;
            for (int b = 0; b < B; b++)
                for (int k = 0; k < 12; k++)
                    if (fabsf(contact_gaussians[(size_t)12 * (b * G + g) + k]) > 1e-9f) act = 1;
            g_active[g] = act;
        }
    }
}

// ---- kernel 2: fused 2D bucket build — hist + scan + scatter, all in smem ----
// grid (B, 2): blockIdx.y selects table (0 = obj_pts, 1 = obj_normals).
__global__ void __launch_bounds__(BTPB)
build_kernel(const float* __restrict__ obj_pts,
             const float* __restrict__ obj_normals,
             int B, int O) {
    int b = blockIdx.x, table = blockIdx.y;
    int tid = threadIdx.x;
    __shared__ int hist[NB2];
    __shared__ int aux[BTPB];
    for (int i = tid; i < NB2; i += BTPB) hist[i] = 0;
    __syncthreads();

    // histogram (smem atomics) over (x,y) bins
    if (table == 0) {
        for (int o = tid; o < O; o += BTPB) {
            size_t i = (size_t)b * O + o;
            atomicAdd(&hist[b2of(obj_pts[3*i+1]) * NBX + b2of(obj_pts[3*i])], 1);
        }
    } else {
        for (int o = tid; o < O; o += BTPB) {
            size_t i = (size_t)b * O + o;
            atomicAdd(&hist[b2of(obj_normals[6*i+1]) * NBX + b2of(obj_normals[6*i])], 1);
        }
    }
    __syncthreads();

    // blocked inclusive scan of 4096 bins: 8 bins/thread serial + scan of partials
    const int BPT = NB2 / BTPB;   // 8
    int base = tid * BPT;
    int vals[BPT];
    int s = 0;
#pragma unroll
    for (int k = 0; k < BPT; k++) { vals[k] = hist[base + k]; s += vals[k]; }
    aux[tid] = s;
    __syncthreads();
    for (int d = 1; d < BTPB; d <<= 1) {
        int v = (tid >= d) ? aux[tid - d] : 0;
        __syncthreads();
        aux[tid] += v;
        __syncthreads();
    }
    int run = (tid == 0) ? 0 : aux[tid - 1];
#pragma unroll
    for (int k = 0; k < BPT; k++) { run += vals[k]; hist[base + k] = run; }  // inclusive
    __syncthreads();

    // write offsets to global (goff[i+1] = inclusive[i]), then make hist exclusive
    int* goff = (table ? g_on2 : g_op2) + b * (NB2 + 1);
    for (int i = tid; i < NB2; i += BTPB) goff[i + 1] = hist[i];
    if (tid == 0) goff[0] = 0;
    int ex[BPT];
#pragma unroll
    for (int k = 0; k < BPT; k++)
        ex[k] = (base + k == 0) ? 0 : hist[base + k - 1];
    __syncthreads();
#pragma unroll
    for (int k = 0; k < BPT; k++) hist[base + k] = ex[k];
    __syncthreads();

    // scatter (smem cursor atomics on now-exclusive hist)
    if (table == 0) {
        for (int o = tid; o < O; o += BTPB) {
            size_t i = (size_t)b * O + o;
            float x = obj_pts[3*i], y = obj_pts[3*i+1], z = obj_pts[3*i+2];
            int pos = atomicAdd(&hist[b2of(y) * NBX + b2of(x)], 1);
            g_spts[(size_t)b * O + pos] = make_float4(x, y, z, x*x + y*y + z*z);
        }
    } else {
        for (int o = tid; o < O; o += BTPB) {
            size_t i = (size_t)b * O + o;
            float a = obj_normals[6*i], c = obj_normals[6*i+1], d = obj_normals[6*i+2];
            int pos = atomicAdd(&hist[b2of(c) * NBX + b2of(a)], 1);
            g_snrm[(size_t)b * O + pos] = make_float4(a, c, d, a*a + c*c + d*d);
            g_nidx[(size_t)b * O + pos] = o;
        }
    }
}

// warp min-reduce knockout round: extract union-minimum of lanes' sorted heads
#define KNOCK_ROUND(mr)                                                       \
    {                                                                         \
        float mv = h0;                                                        \
        for (int o_ = 16; o_; o_ >>= 1)                                       \
            mv = fminf(mv, __shfl_xor_sync(0xFFFFFFFFu, mv, o_));             \
        mr = mv;                                                              \
        if (h0 == mv) { h0 = h1; h1 = h2; h2 = h3; h3 = h4; h4 = CUDART_INF_F; } \
    }

// scan a contiguous bucket range [rowbase+x0, rowbase+x1] for top-5 keys
#define SCAN5(x0_, x1_, row_)                                                 \
    {                                                                         \
        int L = offP[(row_) * NBX + (x0_)] + lane;                            \
        int R = offP[(row_) * NBX + (x1_) + 1];                               \
        for (int i = L; i < R; i += 32) {                                     \
            float4 p = P[i];                                                  \
            float k = fmaf(p.x, c0, fmaf(p.y, c1, fmaf(p.z, c2, p.w)));       \
            insert5(k, t0, t1, t2, t3, t4);                                   \
        }                                                                     \
    }

// scan a contiguous bucket range for argmin (key, original index)
#define SCAN1(x0_, x1_, row_)                                                 \
    {                                                                         \
        int L = offN[(row_) * NBX + (x0_)] + lane;                            \
        int R = offN[(row_) * NBX + (x1_) + 1];                               \
        for (int i = L; i < R; i += 32) {                                     \
            float4 q = Q[i];                                                  \
            float k = fmaf(q.x, c0, fmaf(q.y, c1, fmaf(q.z, c2, q.w)));       \
            int oi = NI[i];                                                   \
            bool better = (k < bk) || (k == bk && oi < bidx);                 \
            bk   = better ? k  : bk;                                          \
            bidx = better ? oi : bidx;                                        \
        }                                                                     \
    }

// min margin (distance from query to nearest window edge); INF if window at domain edge
#define MARGIN2(xl_, xh_, yl_, yh_, mg_)                                      \
    {                                                                         \
        float mxl = ((xl_) == 0)       ? CUDART_INF_F : vx - (XMIN2 + (xl_) * W2);       \
        float mxh = ((xh_) == NBX - 1) ? CUDART_INF_F : (XMIN2 + ((xh_) + 1) * W2) - vx; \
        float myl = ((yl_) == 0)       ? CUDART_INF_F : vy - (XMIN2 + (yl_) * W2);       \
        float myh = ((yh_) == NBX - 1) ? CUDART_INF_F : (XMIN2 + ((yh_) + 1) * W2) - vy; \
        mg_ = fminf(fminf(mxl, mxh), fminf(myl, myh));                        \
    }

// ---- kernel 3: warp-per-vertex 2D-windowed exact 5-NN + NN-normal + epilogue ----
__global__ void __launch_bounds__(QTPB)
query_kernel(const float* __restrict__ verts,
             const float* __restrict__ obj_normals,
             int B, int V, int O, int G) {
    int wid  = (blockIdx.x * QTPB + threadIdx.x) >> 5;
    int lane = threadIdx.x & 31;
    float pc = 0.0f;

    if (wid < B * V) {
        int b = wid / V, v = wid - b * V;
        const float* vp = verts + (size_t)3 * wid;
        float vx = vp[0], vy = vp[1], vz = vp[2];
        float c0 = -2.0f * vx, c1 = -2.0f * vy, c2 = -2.0f * vz;
        float v2 = vx*vx + vy*vy + vz*vz;
        int cbx = b2of(vx), cby = b2of(vy);

        // ===== phase 1: exact 5-NN over 2D-bucketed obj_pts =====
        const float4* P = g_spts + (size_t)b * O;
        const int* offP = g_op2 + b * (NB2 + 1);
        float t0, t1, t2, t3, t4;
        t0 = t1 = t2 = t3 = t4 = CUDART_INF_F;
        int xlo = max(cbx - HWP, 0), xhi = min(cbx + HWP, NBX - 1);
        int ylo = max(cby - HWP, 0), yhi = min(cby + HWP, NBX - 1);
        for (int y = ylo; y <= yhi; y++) SCAN5(xlo, xhi, y);

        float m0, m1, m2, m3, m4;
        for (;;) {
            float h0 = t0, h1 = t1, h2 = t2, h3 = t3, h4 = t4;
            KNOCK_ROUND(m0); KNOCK_ROUND(m1); KNOCK_ROUND(m2);
            KNOCK_ROUND(m3); KNOCK_ROUND(m4);
            float mg; MARGIN2(xlo, xhi, ylo, yhi, mg);
            if (mg * mg >= m4 + v2) break;   // exact: outside window is farther
            int nxlo = max(xlo - EWP, 0), nxhi = min(xhi + EWP, NBX - 1);
            int nylo = max(ylo - EWP, 0), nyhi = min(yhi + EWP, NBX - 1);
            // rim only (no duplicates): new rows full width, old rows side strips
            for (int y = nylo; y < ylo; y++)  SCAN5(nxlo, nxhi, y);
            for (int y = yhi + 1; y <= nyhi; y++) SCAN5(nxlo, nxhi, y);
            if (nxlo < xlo) for (int y = ylo; y <= yhi; y++) SCAN5(nxlo, xlo - 1, y);
            if (nxhi > xhi) for (int y = ylo; y <= yhi; y++) SCAN5(xhi + 1, nxhi, y);
            xlo = nxlo; xhi = nxhi; ylo = nylo; yhi = nyhi;
        }
        float sk = sqrtf(fmaxf(m0 + v2, 0.f)) + sqrtf(fmaxf(m1 + v2, 0.f))
                 + sqrtf(fmaxf(m2 + v2, 0.f)) + sqrtf(fmaxf(m3 + v2, 0.f))
                 + sqrtf(fmaxf(m4 + v2, 0.f));

        // ===== phase 2: exact NN over 2D-bucketed normals (argmin, tie->min idx) =====
        const float4* Q = g_snrm + (size_t)b * O;
        const int* NI   = g_nidx + (size_t)b * O;
        const int* offN = g_on2 + b * (NB2 + 1);
        float bk = CUDART_INF_F; int bidx = 0x7FFFFFFF;
        xlo = max(cbx - HWN, 0); xhi = min(cbx + HWN, NBX - 1);
        ylo = max(cby - HWN, 0); yhi = min(cby + HWN, NBX - 1);
        for (int y = ylo; y <= yhi; y++) SCAN1(xlo, xhi, y);

        int ui; float uk;
        for (;;) {
            uk = bk; ui = bidx;
            for (int o_ = 16; o_; o_ >>= 1) {
                float ok = __shfl_xor_sync(0xFFFFFFFFu, uk, o_);
                int   oi = __shfl_xor_sync(0xFFFFFFFFu, ui, o_);
                if (ok < uk || (ok == uk && oi < ui)) { uk = ok; ui = oi; }
            }
            float mg; MARGIN2(xlo, xhi, ylo, yhi, mg);
            if (mg * mg >= uk + v2) break;
            int nxlo = max(xlo - EWN, 0), nxhi = min(xhi + EWN, NBX - 1);
            int nylo = max(ylo - EWN, 0), nyhi = min(yhi + EWN, NBX - 1);
            for (int y = nylo; y < ylo; y++)  SCAN1(nxlo, nxhi, y);
            for (int y = yhi + 1; y <= nyhi; y++) SCAN1(nxlo, nxhi, y);
            if (nxlo < xlo) for (int y = ylo; y <= yhi; y++) SCAN1(nxlo, xlo - 1, y);
            if (nxhi > xhi) for (int y = ylo; y <= yhi; y++) SCAN1(xhi + 1, nxhi, y);
            xlo = nxlo; xhi = nxhi; ylo = nylo; yhi = nyhi;
        }

        // ===== epilogue (lane 0): knn sum, gaussian weight, pen =====
        if (lane == 0) {
            g_sknn[wid] = sk;
            int g = g_gid[v];
            const float* C = g_chol + 10 * (b * G + g);
            float dx = vx - C[7], dy = vy - C[8], dz = vz - C[9];
            float y0 = dx * C[3];
            float y1 = (dy - C[0] * y0) * C[4];
            float y2 = (dz - C[1] * y0 - C[2] * y1) * C[5];
            float maha = y0*y0 + y1*y1 + y2*y2;
            float logp = -0.5f * (maha + 3.0f * F_LOG2PI) - C[6];
            float w = expf(logp);
            g_w[wid] = w;
            atomicMin(&g_mnbits[b * G + g], __float_as_int(w));
            atomicMax(&g_mxbits[b * G + g], __float_as_int(w));

            const float* nn = obj_normals + 6 * ((size_t)b * O + ui);
            float px = nn[0], py = nn[1], pz = nn[2];
            float nx = nn[3], ny = nn[4], nz = nn[5];
            float rx = px - 0.002f * nx, ry = py - 0.002f * ny, rz = pz - 0.002f * nz;
            float dp = nx * (vx - rx) + ny * (vy - ry) + nz * (vz - rz);
            pc = fmaxf(-dp, 0.0f);
        }
    }

    __shared__ float red[QTPB / 32];
    if (lane == 0) red[threadIdx.x >> 5] = pc;
    __syncthreads();
    if (threadIdx.x == 0) {
        float s = 0.0f;
        for (int i = 0; i < QTPB / 32; i++) s += red[i];
        atomicAdd(&g_pacc, (double)s);
    }
}

// ---- kernel 4: normalized/thresholded weights * knn sums -> d accumulator ----
__global__ void final_kernel(int B, int V, int G) {
    int idx = blockIdx.x * 256 + threadIdx.x;
    float c = 0.0f;
    if (idx < B * V) {
        int b = idx / V, v = idx - b * V;
        int g = g_gid[v];
        float w  = g_w[idx];
        float mn = __int_as_float(g_mnbits[b * G + g]);
        float mx = __int_as_float(g_mxbits[b * G + g]);
        float wn = (w - mn) / (mx - mn);
        if (!(wn > 0.01f)) wn = 0.0f;          // NaN-safe threshold
        if (!g_active[g]) wn = 0.0f;
        c = wn * g_sknn[idx];
    }
    __shared__ float red[256];
    red[threadIdx.x] = c;
    __syncthreads();
    for (int s = 128; s > 0; s >>= 1) {
        if (threadIdx.x < s) red[threadIdx.x] += red[threadIdx.x + s];
        __syncthreads();
    }
    if (threadIdx.x == 0) atomicAdd(&g_dacc, (double)red[0]);
}

// ---- kernel 5: write outputs ----
__global__ void out_kernel(float* out, int B, int V, int K, int out_size) {
    if (out_size >= 1) out[0] = (float)(g_dacc / ((double)B * V * K));
    if (out_size >= 2) out[1] = (float)(g_pacc / ((double)B * V));
}

extern "C" void kernel_launch(void* const* d_in, const int* in_sizes, int n_in,
                              void* d_out, int out_size) {
    const float* verts         = (const float*)d_in[0];
    const float* anchor_verts  = (const float*)d_in[1];
    const float* obj_pts       = (const float*)d_in[2];
    const float* cg            = (const float*)d_in[3];
    const float* obj_normals   = (const float*)d_in[4];
    const float* init_verts    = (const float*)d_in[5];
    const float* init_anchors  = (const float*)d_in[6];

    int V = in_sizes[5] / 3;          // 778
    int G = in_sizes[6] / 3;          // 32
    int B = in_sizes[0] / (3 * V);    // 16
    int O = in_sizes[2] / (3 * B);    // 8192
    int K = 5;

    init_kernel<<<2, 256>>>(init_verts, init_anchors, cg, anchor_verts, B, V, G);
    build_kernel<<<dim3(B, 2), BTPB>>>(obj_pts, obj_normals, B, O);

    int warps = B * V;
    int qBlocks = (warps * 32 + QTPB - 1) / QTPB;
    query_kernel<<<qBlocks, QTPB>>>(verts, obj_normals, B, V, O, G);

    int rb = (B * V + 255) / 256;
    final_kernel<<<rb, 256>>>(B, V, G);
    out_kernel<<<1, 1>>>((float*)d_out, B, V, K, out_size);
}

// round 13
// speedup vs baseline: 1.1473x; 1.1473x over previous
#include <cuda_runtime.h>
#include <math_constants.h>

// Problem constants
#define GG      32
#define MAXB    16
#define MAXV    1024
#define MAXO    8192
#define NBX     64
#define NB2     (NBX * NBX)
#define XMIN2   (-4.0f)
#define W2      0.125f            // 8/64, exact power of two
#define INV2    8.0f
#define HWP     3                 // initial half-window, 5-NN phase (tail-safe: margin 0.375)
#define EWP     2                 // expansion step
#define HWN     2                 // initial half-window, 1-NN phase (tail-safe: margin 0.25)
#define EWN     2
#define QTPB    256
#define BTPB    512
#define F_LOG2PI 1.8378770664093453f

// ---- scratch (static device globals: no allocation allowed) ----
__device__ float4 g_spts[MAXB * MAXO];     // (x,y)-bucketed {x,y,z,|p|^2}
__device__ float4 g_snrm[MAXB * MAXO];     // (x,y)-bucketed {nx,ny,nz,|n|^2}
__device__ int    g_nidx[MAXB * MAXO];     // original per-batch index of bucketed normal
__device__ int    g_op2[MAXB * (NB2 + 1)]; // exclusive offsets (points)
__device__ int    g_on2[MAXB * (NB2 + 1)]; // exclusive offsets (normals)
__device__ int    g_gid[MAXV];
__device__ float  g_chol[MAXB * GG * 10];
__device__ int    g_active[GG];
__device__ float  g_w[MAXB * MAXV];
__device__ float  g_sknn[MAXB * MAXV];
__device__ int    g_mnbits[MAXB * GG];
__device__ int    g_mxbits[MAXB * GG];
__device__ double g_dacc;
__device__ double g_pacc;

__device__ __forceinline__ int b2of(float x) {
    int bk = (int)floorf((x - XMIN2) * INV2);
    return bk < 0 ? 0 : (bk > NBX - 1 ? NBX - 1 : bk);
}

// Branchless sorted insert (ascending t0..t4 kept 5-smallest). 9 ops.
__device__ __forceinline__ void insert5(float a, float& t0, float& t1, float& t2,
                                        float& t3, float& t4) {
    float n0 = fminf(t0, a); a = fmaxf(t0, a);
    float n1 = fminf(t1, a); a = fmaxf(t1, a);
    float n2 = fminf(t2, a); a = fmaxf(t2, a);
    float n3 = fminf(t3, a); a = fmaxf(t3, a);
    float n4 = fminf(t4, a);
    t0 = n0; t1 = n1; t2 = n2; t3 = n3; t4 = n4;
}

// ---- kernel 1: gid; Cholesky; active; accumulator init ----
__global__ void init_kernel(const float* __restrict__ init_verts,
                            const float* __restrict__ init_anchors,
                            const float* __restrict__ contact_gaussians,
                            const float* __restrict__ anchor_verts,
                            int B, int V, int G) {
    int bi = blockIdx.x, tid = threadIdx.x;
    if (bi == 0) {
        for (int v = tid; v < V; v += 256) {
            float vx = init_verts[3*v], vy = init_verts[3*v+1], vz = init_verts[3*v+2];
            float best = CUDART_INF_F; int bg = 0;
            for (int g = 0; g < G; g++) {
                float dx = vx - init_anchors[3*g];
                float dy = vy - init_anchors[3*g+1];
                float dz = vz - init_anchors[3*g+2];
                float d2 = dx*dx + dy*dy + dz*dz;
                if (d2 < best) { best = d2; bg = g; }
            }
            g_gid[v] = bg;
        }
    } else {
        if (tid == 0) { g_dacc = 0.0; g_pacc = 0.0; }
        for (int i = tid; i < B * G; i += 256) {
            g_mnbits[i] = 0x7F800000;   // +inf
            g_mxbits[i] = 0;            // 0.0f acts as -inf (w >= 0)
        }
        for (int i = tid; i < B * G; i += 256) {
            const float* cg = contact_gaussians + (size_t)12 * i;
            float mx_ = cg[0] + anchor_verts[3*i+0];
            float my_ = cg[1] + anchor_verts[3*i+1];
            float mz_ = cg[2] + anchor_verts[3*i+2];
            float a00 = cg[3], a10 = cg[6], a11 = cg[7];
            float a20 = cg[9], a21 = cg[10], a22 = cg[11];
            float l00 = sqrtf(a00);
            float l10 = a10 / l00;
            float l20 = a20 / l00;
            float l11 = sqrtf(a11 - l10 * l10);
            float l21 = (a21 - l20 * l10) / l11;
            float l22 = sqrtf(a22 - l20 * l20 - l21 * l21);
            float hld = logf(l00) + logf(l11) + logf(l22);
            float* C = g_chol + 10 * i;
            C[0] = l10; C[1] = l20; C[2] = l21;
            C[3] = 1.0f / l00; C[4] = 1.0f / l11; C[5] = 1.0f / l22;
            C[6] = hld; C[7] = mx_; C[8] = my_; C[9] = mz_;
        }
        for (int g = tid; g < G; g += 256) {
            int act = 0;
            for (int b = 0; b < B; b++)
                for (int k = 0; k < 12; k++)
                    if (fabsf(contact_gaussians[(size_t)12 * (b * G + g) + k]) > 1e-9f) act = 1;
            g_active[g] = act;
        }
    }
}

// ---- kernel 2: fused 2D bucket build — hist + scan + scatter, all in smem ----
// grid (B, 2): blockIdx.y selects table (0 = obj_pts, 1 = obj_normals).
__global__ void __launch_bounds__(BTPB)
build_kernel(const float* __restrict__ obj_pts,
             const float* __restrict__ obj_normals,
             int B, int O) {
    int b = blockIdx.x, table = blockIdx.y;
    int tid = threadIdx.x;
    __shared__ int hist[NB2];
    __shared__ int aux[BTPB];
    for (int i = tid; i < NB2; i += BTPB) hist[i] = 0;
    __syncthreads();

    // histogram (smem atomics) over (x,y) bins
    if (table == 0) {
        for (int o = tid; o < O; o += BTPB) {
            size_t i = (size_t)b * O + o;
            atomicAdd(&hist[b2of(obj_pts[3*i+1]) * NBX + b2of(obj_pts[3*i])], 1);
        }
    } else {
        for (int o = tid; o < O; o += BTPB) {
            size_t i = (size_t)b * O + o;
            atomicAdd(&hist[b2of(obj_normals[6*i+1]) * NBX + b2of(obj_normals[6*i])], 1);
        }
    }
    __syncthreads();

    // blocked inclusive scan of 4096 bins: 8 bins/thread serial + scan of partials
    const int BPT = NB2 / BTPB;   // 8
    int base = tid * BPT;
    int vals[BPT];
    int s = 0;
#pragma unroll
    for (int k = 0; k < BPT; k++) { vals[k] = hist[base + k]; s += vals[k]; }
    aux[tid] = s;
    __syncthreads();
    for (int d = 1; d < BTPB; d <<= 1) {
        int v = (tid >= d) ? aux[tid - d] : 0;
        __syncthreads();
        aux[tid] += v;
        __syncthreads();
    }
    int run = (tid == 0) ? 0 : aux[tid - 1];
#pragma unroll
    for (int k = 0; k < BPT; k++) { run += vals[k]; hist[base + k] = run; }  // inclusive
    __syncthreads();

    // write offsets to global (goff[i+1] = inclusive[i]), then make hist exclusive
    int* goff = (table ? g_on2 : g_op2) + b * (NB2 + 1);
    for (int i = tid; i < NB2; i += BTPB) goff[i + 1] = hist[i];
    if (tid == 0) goff[0] = 0;
    int ex[BPT];
#pragma unroll
    for (int k = 0; k < BPT; k++)
        ex[k] = (base + k == 0) ? 0 : hist[base + k - 1];
    __syncthreads();
#pragma unroll
    for (int k = 0; k < BPT; k++) hist[base + k] = ex[k];
    __syncthreads();

    // scatter (smem cursor atomics on now-exclusive hist)
    if (table == 0) {
        for (int o = tid; o < O; o += BTPB) {
            size_t i = (size_t)b * O + o;
            float x = obj_pts[3*i], y = obj_pts[3*i+1], z = obj_pts[3*i+2];
            int pos = atomicAdd(&hist[b2of(y) * NBX + b2of(x)], 1);
            g_spts[(size_t)b * O + pos] = make_float4(x, y, z, x*x + y*y + z*z);
        }
    } else {
        for (int o = tid; o < O; o += BTPB) {
            size_t i = (size_t)b * O + o;
            float a = obj_normals[6*i], c = obj_normals[6*i+1], d = obj_normals[6*i+2];
            int pos = atomicAdd(&hist[b2of(c) * NBX + b2of(a)], 1);
            g_snrm[(size_t)b * O + pos] = make_float4(a, c, d, a*a + c*c + d*d);
            g_nidx[(size_t)b * O + pos] = o;
        }
    }
}

// warp min-reduce knockout round: extract union-minimum of lanes' sorted heads
#define KNOCK_ROUND(mr)                                                       \
    {                                                                         \
        float mv = h0;                                                        \
        for (int o_ = 16; o_; o_ >>= 1)                                       \
            mv = fminf(mv, __shfl_xor_sync(0xFFFFFFFFu, mv, o_));             \
        mr = mv;                                                              \
        if (h0 == mv) { h0 = h1; h1 = h2; h2 = h3; h3 = h4; h4 = CUDART_INF_F; } \
    }

// scan a contiguous bucket range [rowbase+x0, rowbase+x1] for top-5 keys
#define SCAN5(x0_, x1_, row_)                                                 \
    {                                                                         \
        int L = offP[(row_) * NBX + (x0_)] + lane;                            \
        int R = offP[(row_) * NBX + (x1_) + 1];                               \
        for (int i = L; i < R; i += 32) {                                     \
            float4 p = P[i];                                                  \
            float k = fmaf(p.x, c0, fmaf(p.y, c1, fmaf(p.z, c2, p.w)));       \
            insert5(k, t0, t1, t2, t3, t4);                                   \
        }                                                                     \
    }

// scan a contiguous bucket range for argmin (key, original index)
#define SCAN1(x0_, x1_, row_)                                                 \
    {                                                                         \
        int L = offN[(row_) * NBX + (x0_)] + lane;                            \
        int R = offN[(row_) * NBX + (x1_) + 1];                               \
        for (int i = L; i < R; i += 32) {                                     \
            float4 q = Q[i];                                                  \
            float k = fmaf(q.x, c0, fmaf(q.y, c1, fmaf(q.z, c2, q.w)));       \
            int oi = NI[i];                                                   \
            bool better = (k < bk) || (k == bk && oi < bidx);                 \
            bk   = better ? k  : bk;                                          \
            bidx = better ? oi : bidx;                                        \
        }                                                                     \
    }

// min margin (distance from query to nearest window edge); INF if window at domain edge
#define MARGIN2(xl_, xh_, yl_, yh_, mg_)                                      \
    {                                                                         \
        float mxl = ((xl_) == 0)       ? CUDART_INF_F : vx - (XMIN2 + (xl_) * W2);       \
        float mxh = ((xh_) == NBX - 1) ? CUDART_INF_F : (XMIN2 + ((xh_) + 1) * W2) - vx; \
        float myl = ((yl_) == 0)       ? CUDART_INF_F : vy - (XMIN2 + (yl_) * W2);       \
        float myh = ((yh_) == NBX - 1) ? CUDART_INF_F : (XMIN2 + ((yh_) + 1) * W2) - vy; \
        mg_ = fminf(fminf(mxl, mxh), fminf(myl, myh));                        \
    }

// ---- kernel 3: warp-per-vertex 2D-windowed exact 5-NN + NN-normal + epilogue ----
__global__ void __launch_bounds__(QTPB)
query_kernel(const float* __restrict__ verts,
             const float* __restrict__ obj_normals,
             int B, int V, int O, int G) {
    int wid  = (blockIdx.x * QTPB + threadIdx.x) >> 5;
    int lane = threadIdx.x & 31;
    float pc = 0.0f;

    if (wid < B * V) {
        int b = wid / V, v = wid - b * V;
        const float* vp = verts + (size_t)3 * wid;
        float vx = vp[0], vy = vp[1], vz = vp[2];
        float c0 = -2.0f * vx, c1 = -2.0f * vy, c2 = -2.0f * vz;
        float v2 = vx*vx + vy*vy + vz*vz;
        int cbx = b2of(vx), cby = b2of(vy);

        // ===== phase 1: exact 5-NN over 2D-bucketed obj_pts =====
        const float4* P = g_spts + (size_t)b * O;
        const int* offP = g_op2 + b * (NB2 + 1);
        float t0, t1, t2, t3, t4;
        t0 = t1 = t2 = t3 = t4 = CUDART_INF_F;
        int xlo = max(cbx - HWP, 0), xhi = min(cbx + HWP, NBX - 1);
        int ylo = max(cby - HWP, 0), yhi = min(cby + HWP, NBX - 1);
        for (int y = ylo; y <= yhi; y++) SCAN5(xlo, xhi, y);

        float m0, m1, m2, m3, m4;
        for (;;) {
            float h0 = t0, h1 = t1, h2 = t2, h3 = t3, h4 = t4;
            KNOCK_ROUND(m0); KNOCK_ROUND(m1); KNOCK_ROUND(m2);
            KNOCK_ROUND(m3); KNOCK_ROUND(m4);
            float mg; MARGIN2(xlo, xhi, ylo, yhi, mg);
            if (mg * mg >= m4 + v2) break;   // exact: outside window is farther
            int nxlo = max(xlo - EWP, 0), nxhi = min(xhi + EWP, NBX - 1);
            int nylo = max(ylo - EWP, 0), nyhi = min(yhi + EWP, NBX - 1);
            // rim only (no duplicates): new rows full width, old rows side strips
            for (int y = nylo; y < ylo; y++)  SCAN5(nxlo, nxhi, y);
            for (int y = yhi + 1; y <= nyhi; y++) SCAN5(nxlo, nxhi, y);
            if (nxlo < xlo) for (int y = ylo; y <= yhi; y++) SCAN5(nxlo, xlo - 1, y);
            if (nxhi > xhi) for (int y = ylo; y <= yhi; y++) SCAN5(xhi + 1, nxhi, y);
            xlo = nxlo; xhi = nxhi; ylo = nylo; yhi = nyhi;
        }
        float sk = sqrtf(fmaxf(m0 + v2, 0.f)) + sqrtf(fmaxf(m1 + v2, 0.f))
                 + sqrtf(fmaxf(m2 + v2, 0.f)) + sqrtf(fmaxf(m3 + v2, 0.f))
                 + sqrtf(fmaxf(m4 + v2, 0.f));

        // ===== phase 2: exact NN over 2D-bucketed normals (argmin, tie->min idx) =====
        const float4* Q = g_snrm + (size_t)b * O;
        const int* NI   = g_nidx + (size_t)b * O;
        const int* offN = g_on2 + b * (NB2 + 1);
        float bk = CUDART_INF_F; int bidx = 0x7FFFFFFF;
        xlo = max(cbx - HWN, 0); xhi = min(cbx + HWN, NBX - 1);
        ylo = max(cby - HWN, 0); yhi = min(cby + HWN, NBX - 1);
        for (int y = ylo; y <= yhi; y++) SCAN1(xlo, xhi, y);

        int ui; float uk;
        for (;;) {
            uk = bk; ui = bidx;
            for (int o_ = 16; o_; o_ >>= 1) {
                float ok = __shfl_xor_sync(0xFFFFFFFFu, uk, o_);
                int   oi = __shfl_xor_sync(0xFFFFFFFFu, ui, o_);
                if (ok < uk || (ok == uk && oi < ui)) { uk = ok; ui = oi; }
            }
            float mg; MARGIN2(xlo, xhi, ylo, yhi, mg);
            if (mg * mg >= uk + v2) break;
            int nxlo = max(xlo - EWN, 0), nxhi = min(xhi + EWN, NBX - 1);
            int nylo = max(ylo - EWN, 0), nyhi = min(yhi + EWN, NBX - 1);
            for (int y = nylo; y < ylo; y++)  SCAN1(nxlo, nxhi, y);
            for (int y = yhi + 1; y <= nyhi; y++) SCAN1(nxlo, nxhi, y);
            if (nxlo < xlo) for (int y = ylo; y <= yhi; y++) SCAN1(nxlo, xlo - 1, y);
            if (nxhi > xhi) for (int y = ylo; y <= yhi; y++) SCAN1(xhi + 1, nxhi, y);
            xlo = nxlo; xhi = nxhi; ylo = nylo; yhi = nyhi;
        }

        // ===== epilogue (lane 0): knn sum, gaussian weight, pen =====
        if (lane == 0) {
            g_sknn[wid] = sk;
            int g = g_gid[v];
            const float* C = g_chol + 10 * (b * G + g);
            float dx = vx - C[7], dy = vy - C[8], dz = vz - C[9];
            float y0 = dx * C[3];
            float y1 = (dy - C[0] * y0) * C[4];
            float y2 = (dz - C[1] * y0 - C[2] * y1) * C[5];
            float maha = y0*y0 + y1*y1 + y2*y2;
            float logp = -0.5f * (maha + 3.0f * F_LOG2PI) - C[6];
            float w = expf(logp);
            g_w[wid] = w;
            atomicMin(&g_mnbits[b * G + g], __float_as_int(w));
            atomicMax(&g_mxbits[b * G + g], __float_as_int(w));

            const float* nn = obj_normals + 6 * ((size_t)b * O + ui);
            float px = nn[0], py = nn[1], pz = nn[2];
            float nx = nn[3], ny = nn[4], nz = nn[5];
            float rx = px - 0.002f * nx, ry = py - 0.002f * ny, rz = pz - 0.002f * nz;
            float dp = nx * (vx - rx) + ny * (vy - ry) + nz * (vz - rz);
            pc = fmaxf(-dp, 0.0f);
        }
    }

    __shared__ float red[QTPB / 32];
    if (lane == 0) red[threadIdx.x >> 5] = pc;
    __syncthreads();
    if (threadIdx.x == 0) {
        float s = 0.0f;
        for (int i = 0; i < QTPB / 32; i++) s += red[i];
        atomicAdd(&g_pacc, (double)s);
    }
}

// ---- kernel 4: normalized/thresholded weights * knn sums -> d accumulator ----
__global__ void final_kernel(int B, int V, int G) {
    int idx = blockIdx.x * 256 + threadIdx.x;
    float c = 0.0f;
    if (idx < B * V) {
        int b = idx / V, v = idx - b * V;
        int g = g_gid[v];
        float w  = g_w[idx];
        float mn = __int_as_float(g_mnbits[b * G + g]);
        float mx = __int_as_float(g_mxbits[b * G + g]);
        float wn = (w - mn) / (mx - mn);
        if (!(wn > 0.01f)) wn = 0.0f;          // NaN-safe threshold
        if (!g_active[g]) wn = 0.0f;
        c = wn * g_sknn[idx];
    }
    __shared__ float red[256];
    red[threadIdx.x] = c;
    __syncthreads();
    for (int s = 128; s > 0; s >>= 1) {
        if (threadIdx.x < s) red[threadIdx.x] += red[threadIdx.x + s];
        __syncthreads();
    }
    if (threadIdx.x == 0) atomicAdd(&g_dacc, (double)red[0]);
}

// ---- kernel 5: write outputs ----
__global__ void out_kernel(float* out, int B, int V, int K, int out_size) {
    if (out_size >= 1) out[0] = (float)(g_dacc / ((double)B * V * K));
    if (out_size >= 2) out[1] = (float)(g_pacc / ((double)B * V));
}

extern "C" void kernel_launch(void* const* d_in, const int* in_sizes, int n_in,
                              void* d_out, int out_size) {
    const float* verts         = (const float*)d_in[0];
    const float* anchor_verts  = (const float*)d_in[1];
    const float* obj_pts       = (const float*)d_in[2];
    const float* cg            = (const float*)d_in[3];
    const float* obj_normals   = (const float*)d_in[4];
    const float* init_verts    = (const float*)d_in[5];
    const float* init_anchors  = (const float*)d_in[6];

    int V = in_sizes[5] / 3;          // 778
    int G = in_sizes[6] / 3;          // 32
    int B = in_sizes[0] / (3 * V);    // 16
    int O = in_sizes[2] / (3 * B);    // 8192
    int K = 5;

    init_kernel<<<2, 256>>>(init_verts, init_anchors, cg, anchor_verts, B, V, G);
    build_kernel<<<dim3(B, 2), BTPB>>>(obj_pts, obj_normals, B, O);

    int warps = B * V;
    int qBlocks = (warps * 32 + QTPB - 1) / QTPB;
    query_kernel<<<qBlocks, QTPB>>>(verts, obj_normals, B, V, O, G);

    int rb = (B * V + 255) / 256;
    final_kernel<<<rb, 256>>>(B, V, G);
    out_kernel<<<1, 1>>>((float*)d_out, B, V, K, out_size);
}

// round 14
// speedup vs baseline: 1.7783x; 1.5501x over previous
#include <cuda_runtime.h>
#include <math_constants.h>

// Problem constants
#define GG      32
#define MAXB    16
#define MAXV    1024
#define MAXO    8192
#define NBUCK   256
#define XMINF   (-4.0f)
#define BW      0.03125f          // 8/256, exact power of two
#define INVW    32.0f
#define HW0     6                 // initial half-window (buckets) — known-good
#define EW      6                 // expansion step (buckets)
#define QTPB    256
#define BTPB    512
#define F_LOG2PI 1.8378770664093453f

// ---- scratch (static device globals: no allocation allowed) ----
__device__ float4 g_spts[MAXB * MAXO];     // x-bucketed {x,y,z,|p|^2}
__device__ float4 g_snrm[MAXB * MAXO];     // x-bucketed {nx,ny,nz, idx_as_float}
__device__ int    g_op[MAXB * (NBUCK + 1)]; // exclusive offsets (points)
__device__ int    g_on[MAXB * (NBUCK + 1)]; // exclusive offsets (normals)
__device__ int    g_gid[MAXV];
__device__ float  g_chol[MAXB * GG * 10];
__device__ int    g_active[GG];
__device__ float  g_w[MAXB * MAXV];
__device__ float  g_sknn[MAXB * MAXV];
__device__ int    g_mnbits[MAXB * GG];
__device__ int    g_mxbits[MAXB * GG];
__device__ double g_dacc;
__device__ double g_pacc;

__device__ __host__ __forceinline__ int bucket_of(float x) {
    int bk = (int)floorf((x - XMINF) * INVW);
    return bk < 0 ? 0 : (bk > NBUCK - 1 ? NBUCK - 1 : bk);
}

// Branchless sorted insert (ascending t0..t4 kept 5-smallest). 9 ops.
__device__ __forceinline__ void insert5(float a, float& t0, float& t1, float& t2,
                                        float& t3, float& t4) {
    float n0 = fminf(t0, a); a = fmaxf(t0, a);
    float n1 = fminf(t1, a); a = fmaxf(t1, a);
    float n2 = fminf(t2, a); a = fmaxf(t2, a);
    float n3 = fminf(t3, a); a = fmaxf(t3, a);
    float n4 = fminf(t4, a);
    t0 = n0; t1 = n1; t2 = n2; t3 = n3; t4 = n4;
}

// ---- kernel 1: fused build + init.
// grid (B, 3): y==0 -> bucket obj_pts; y==1 -> bucket obj_normals;
//              y==2 -> init work (gid / chol / active / accumulators).
__global__ void __launch_bounds__(BTPB)
build_kernel(const float* __restrict__ obj_pts,
             const float* __restrict__ obj_normals,
             const float* __restrict__ init_verts,
             const float* __restrict__ init_anchors,
             const float* __restrict__ contact_gaussians,
             const float* __restrict__ anchor_verts,
             int B, int V, int O, int G) {
    int b = blockIdx.x, table = blockIdx.y;
    int tid = threadIdx.x;

    if (table == 2) {
        if (b == 0) {
            // gid[v] = argmin_g dist(init_verts[v], init_anchors[g]) (strict <)
            for (int v = tid; v < V; v += BTPB) {
                float vx = init_verts[3*v], vy = init_verts[3*v+1], vz = init_verts[3*v+2];
                float best = CUDART_INF_F; int bg = 0;
                for (int g = 0; g < G; g++) {
                    float dx = vx - init_anchors[3*g];
                    float dy = vy - init_anchors[3*g+1];
                    float dz = vz - init_anchors[3*g+2];
                    float d2 = dx*dx + dy*dy + dz*dz;
                    if (d2 < best) { best = d2; bg = g; }
                }
                g_gid[v] = bg;
            }
        } else if (b == 1) {
            if (tid == 0) { g_dacc = 0.0; g_pacc = 0.0; }
            for (int i = tid; i < B * G; i += BTPB) {
                g_mnbits[i] = 0x7F800000;   // +inf
                g_mxbits[i] = 0;            // 0.0f acts as -inf (w >= 0)
            }
            for (int i = tid; i < B * G; i += BTPB) {
                const float* cg = contact_gaussians + (size_t)12 * i;
                float mx_ = cg[0] + anchor_verts[3*i+0];
                float my_ = cg[1] + anchor_verts[3*i+1];
                float mz_ = cg[2] + anchor_verts[3*i+2];
                float a00 = cg[3], a10 = cg[6], a11 = cg[7];
                float a20 = cg[9], a21 = cg[10], a22 = cg[11];
                float l00 = sqrtf(a00);
                float l10 = a10 / l00;
                float l20 = a20 / l00;
                float l11 = sqrtf(a11 - l10 * l10);
                float l21 = (a21 - l20 * l10) / l11;
                float l22 = sqrtf(a22 - l20 * l20 - l21 * l21);
                float hld = logf(l00) + logf(l11) + logf(l22);
                float* C = g_chol + 10 * i;
                C[0] = l10; C[1] = l20; C[2] = l21;
                C[3] = 1.0f / l00; C[4] = 1.0f / l11; C[5] = 1.0f / l22;
                C[6] = hld; C[7] = mx_; C[8] = my_; C[9] = mz_;
            }
            for (int g = tid; g < G; g += BTPB) {
                int act = 0;
                for (int bb = 0; bb < B; bb++)
                    for (int k = 0; k < 12; k++)
                        if (fabsf(contact_gaussians[(size_t)12 * (bb * G + g) + k]) > 1e-9f) act = 1;
                g_active[g] = act;
            }
        }
        return;
    }

    __shared__ int s[NBUCK];     // hist -> inclusive scan
    __shared__ int cur[NBUCK];   // scatter cursors
    for (int i = tid; i < NBUCK; i += BTPB) s[i] = 0;
    __syncthreads();

    // histogram (smem atomics)
    if (table == 0) {
        for (int o = tid; o < O; o += BTPB)
            atomicAdd(&s[bucket_of(obj_pts[3 * ((size_t)b * O + o)])], 1);
    } else {
        for (int o = tid; o < O; o += BTPB)
            atomicAdd(&s[bucket_of(obj_normals[6 * ((size_t)b * O + o)])], 1);
    }
    __syncthreads();

    // Hillis-Steele inclusive scan over 256 bins (all threads hit the syncs)
    for (int d = 1; d < NBUCK; d <<= 1) {
        int v = 0;
        if (tid < NBUCK && tid >= d) v = s[tid - d];
        __syncthreads();
        if (tid < NBUCK) s[tid] += v;
        __syncthreads();
    }
    // offsets to global; cursors = exclusive scan
    int* goff = (table ? g_on : g_op) + b * (NBUCK + 1);
    if (tid < NBUCK) {
        goff[tid + 1] = s[tid];
        cur[tid] = (tid == 0) ? 0 : s[tid - 1];
    }
    if (tid == 0) goff[0] = 0;
    __syncthreads();

    // scatter (smem cursor atomics)
    if (table == 0) {
        for (int o = tid; o < O; o += BTPB) {
            size_t i = (size_t)b * O + o;
            float x = obj_pts[3*i], y = obj_pts[3*i+1], z = obj_pts[3*i+2];
            int pos = atomicAdd(&cur[bucket_of(x)], 1);
            g_spts[(size_t)b * O + pos] = make_float4(x, y, z, x*x + y*y + z*z);
        }
    } else {
        for (int o = tid; o < O; o += BTPB) {
            size_t i = (size_t)b * O + o;
            float a = obj_normals[6*i], c = obj_normals[6*i+1], d = obj_normals[6*i+2];
            int pos = atomicAdd(&cur[bucket_of(a)], 1);
            // pack original index into .w; |n|^2 recomputed at query time
            g_snrm[(size_t)b * O + pos] = make_float4(a, c, d, __int_as_float(o));
        }
    }
}

// warp min-reduce knockout round: extract union-minimum of lanes' sorted heads
#define KNOCK_ROUND(mr)                                                       \
    {                                                                         \
        float mv = h0;                                                        \
        for (int o_ = 16; o_; o_ >>= 1)                                       \
            mv = fminf(mv, __shfl_xor_sync(0xFFFFFFFFu, mv, o_));             \
        mr = mv;                                                              \
        if (h0 == mv) { h0 = h1; h1 = h2; h2 = h3; h3 = h4; h4 = CUDART_INF_F; } \
    }

// ---- kernel 2: warp-per-vertex windowed exact 5-NN + NN-normal + epilogue ----
__global__ void __launch_bounds__(QTPB)
query_kernel(const float* __restrict__ verts,
             const float* __restrict__ obj_normals,
             int B, int V, int O, int G) {
    int wid  = (blockIdx.x * QTPB + threadIdx.x) >> 5;
    int lane = threadIdx.x & 31;
    float pc = 0.0f;

    if (wid < B * V) {
        int b = wid / V, v = wid - b * V;
        const float* vp = verts + (size_t)3 * wid;
        float vx = vp[0], vy = vp[1], vz = vp[2];
        float c0 = -2.0f * vx, c1 = -2.0f * vy, c2 = -2.0f * vz;
        float v2 = vx*vx + vy*vy + vz*vz;
        int cb = bucket_of(vx);

        // ===== phase 1: exact 5-NN over bucketed obj_pts =====
        const float4* P   = g_spts + (size_t)b * O;
        const int* offP   = g_op + b * (NBUCK + 1);
        float t0, t1, t2, t3, t4;
        t0 = t1 = t2 = t3 = t4 = CUDART_INF_F;
        int blo = max(cb - HW0, 0), bhi = min(cb + HW0 + 1, NBUCK);
        {
            int R = offP[bhi];
            for (int i = offP[blo] + lane; i < R; i += 32) {
                float4 p = P[i];
                float k = fmaf(p.x, c0, fmaf(p.y, c1, fmaf(p.z, c2, p.w)));
                insert5(k, t0, t1, t2, t3, t4);
            }
        }
        float m0, m1, m2, m3, m4;
        for (;;) {
            float h0 = t0, h1 = t1, h2 = t2, h3 = t3, h4 = t4;
            KNOCK_ROUND(m0); KNOCK_ROUND(m1); KNOCK_ROUND(m2);
            KNOCK_ROUND(m3); KNOCK_ROUND(m4);
            float mlo = (blo == 0)     ? CUDART_INF_F : vx - (XMINF + blo * BW);
            float mhi = (bhi == NBUCK) ? CUDART_INF_F : (XMINF + bhi * BW) - vx;
            float mg = fminf(mlo, mhi);
            if (mg * mg >= m4 + v2) break;   // exact: outside points are farther
            int nlo = max(blo - EW, 0), nhi = min(bhi + EW, NBUCK);
            int Rl = offP[blo];
            for (int i = offP[nlo] + lane; i < Rl; i += 32) {
                float4 p = P[i];
                float k = fmaf(p.x, c0, fmaf(p.y, c1, fmaf(p.z, c2, p.w)));
                insert5(k, t0, t1, t2, t3, t4);
            }
            int Rr = offP[nhi];
            for (int i = offP[bhi] + lane; i < Rr; i += 32) {
                float4 p = P[i];
                float k = fmaf(p.x, c0, fmaf(p.y, c1, fmaf(p.z, c2, p.w)));
                insert5(k, t0, t1, t2, t3, t4);
            }
            blo = nlo; bhi = nhi;
        }
        float sk = sqrtf(fmaxf(m0 + v2, 0.f)) + sqrtf(fmaxf(m1 + v2, 0.f))
                 + sqrtf(fmaxf(m2 + v2, 0.f)) + sqrtf(fmaxf(m3 + v2, 0.f))
                 + sqrtf(fmaxf(m4 + v2, 0.f));

        // ===== phase 2: exact NN over bucketed normals (argmin, tie->min idx) =====
        // index packed in .w; |n|^2 recomputed (fixed expression for determinism)
        const float4* Q   = g_snrm + (size_t)b * O;
        const int* offN   = g_on + b * (NBUCK + 1);
        float bk = CUDART_INF_F; int bidx = 0x7FFFFFFF;
        blo = max(cb - HW0, 0); bhi = min(cb + HW0 + 1, NBUCK);
        {
            int R = offN[bhi];
            for (int i = offN[blo] + lane; i < R; i += 32) {
                float4 q = Q[i];
                float w2 = fmaf(q.x, q.x, fmaf(q.y, q.y, q.z * q.z));
                float k = fmaf(q.x, c0, fmaf(q.y, c1, fmaf(q.z, c2, w2)));
                int oi = __float_as_int(q.w);
                bool better = (k < bk) || (k == bk && oi < bidx);
                bk   = better ? k  : bk;
                bidx = better ? oi : bidx;
            }
        }
        int ui; float uk;
        for (;;) {
            uk = bk; ui = bidx;
            for (int o_ = 16; o_; o_ >>= 1) {
                float ok = __shfl_xor_sync(0xFFFFFFFFu, uk, o_);
                int   oi = __shfl_xor_sync(0xFFFFFFFFu, ui, o_);
                if (ok < uk || (ok == uk && oi < ui)) { uk = ok; ui = oi; }
            }
            float mlo = (blo == 0)     ? CUDART_INF_F : vx - (XMINF + blo * BW);
            float mhi = (bhi == NBUCK) ? CUDART_INF_F : (XMINF + bhi * BW) - vx;
            float mg = fminf(mlo, mhi);
            if (mg * mg >= uk + v2) break;
            int nlo = max(blo - EW, 0), nhi = min(bhi + EW, NBUCK);
            int Rl = offN[blo];
            for (int i = offN[nlo] + lane; i < Rl; i += 32) {
                float4 q = Q[i];
                float w2 = fmaf(q.x, q.x, fmaf(q.y, q.y, q.z * q.z));
                float k = fmaf(q.x, c0, fmaf(q.y, c1, fmaf(q.z, c2, w2)));
                int oi = __float_as_int(q.w);
                bool better = (k < bk) || (k == bk && oi < bidx);
                bk   = better ? k  : bk;
                bidx = better ? oi : bidx;
            }
            int Rr = offN[nhi];
            for (int i = offN[bhi] + lane; i < Rr; i += 32) {
                float4 q = Q[i];
                float w2 = fmaf(q.x, q.x, fmaf(q.y, q.y, q.z * q.z));
                float k = fmaf(q.x, c0, fmaf(q.y, c1, fmaf(q.z, c2, w2)));
                int oi = __float_as_int(q.w);
                bool better = (k < bk) || (k == bk && oi < bidx);
                bk   = better ? k  : bk;
                bidx = better ? oi : bidx;
            }
            blo = nlo; bhi = nhi;
        }

        // ===== epilogue (lane 0): knn sum, gaussian weight, pen =====
        if (lane == 0) {
            g_sknn[wid] = sk;
            int g = g_gid[v];
            const float* C = g_chol + 10 * (b * G + g);
            float dx = vx - C[7], dy = vy - C[8], dz = vz - C[9];
            float y0 = dx * C[3];
            float y1 = (dy - C[0] * y0) * C[4];
            float y2 = (dz - C[1] * y0 - C[2] * y1) * C[5];
            float maha = y0*y0 + y1*y1 + y2*y2;
            float logp = -0.5f * (maha + 3.0f * F_LOG2PI) - C[6];
            float w = expf(logp);
            g_w[wid] = w;
            atomicMin(&g_mnbits[b * G + g], __float_as_int(w));
            atomicMax(&g_mxbits[b * G + g], __float_as_int(w));

            const float* nn = obj_normals + 6 * ((size_t)b * O + ui);
            float px = nn[0], py = nn[1], pz = nn[2];
            float nx = nn[3], ny = nn[4], nz = nn[5];
            float rx = px - 0.002f * nx, ry = py - 0.002f * ny, rz = pz - 0.002f * nz;
            float dp = nx * (vx - rx) + ny * (vy - ry) + nz * (vz - rz);
            pc = fmaxf(-dp, 0.0f);
        }
    }

    __shared__ float red[QTPB / 32];
    if (lane == 0) red[threadIdx.x >> 5] = pc;
    __syncthreads();
    if (threadIdx.x == 0) {
        float s = 0.0f;
        for (int i = 0; i < QTPB / 32; i++) s += red[i];
        atomicAdd(&g_pacc, (double)s);
    }
}

// ---- kernel 3: normalized/thresholded weights * knn sums -> d accumulator ----
__global__ void final_kernel(int B, int V, int G) {
    int idx = blockIdx.x * 256 + threadIdx.x;
    float c = 0.0f;
    if (idx < B * V) {
        int b = idx / V, v = idx - b * V;
        int g = g_gid[v];
        float w  = g_w[idx];
        float mn = __int_as_float(g_mnbits[b * G + g]);
        float mx = __int_as_float(g_mxbits[b * G + g]);
        float wn = (w - mn) / (mx - mn);
        if (!(wn > 0.01f)) wn = 0.0f;          // NaN-safe threshold
        if (!g_active[g]) wn = 0.0f;
        c = wn * g_sknn[idx];
    }
    __shared__ float red[256];
    red[threadIdx.x] = c;
    __syncthreads();
    for (int s = 128; s > 0; s >>= 1) {
        if (threadIdx.x < s) red[threadIdx.x] += red[threadIdx.x + s];
        __syncthreads();
    }
    if (threadIdx.x == 0) atomicAdd(&g_dacc, (double)red[0]);
}

// ---- kernel 4: write outputs ----
__global__ void out_kernel(float* out, int B, int V, int K, int out_size) {
    if (out_size >= 1) out[0] = (float)(g_dacc / ((double)B * V * K));
    if (out_size >= 2) out[1] = (float)(g_pacc / ((double)B * V));
}

extern "C" void kernel_launch(void* const* d_in, const int* in_sizes, int n_in,
                              void* d_out, int out_size) {
    const float* verts         = (const float*)d_in[0];
    const float* anchor_verts  = (const float*)d_in[1];
    const float* obj_pts       = (const float*)d_in[2];
    const float* cg            = (const float*)d_in[3];
    const float* obj_normals   = (const float*)d_in[4];
    const float* init_verts    = (const float*)d_in[5];
    const float* init_anchors  = (const float*)d_in[6];

    int V = in_sizes[5] / 3;          // 778
    int G = in_sizes[6] / 3;          // 32
    int B = in_sizes[0] / (3 * V);    // 16
    int O = in_sizes[2] / (3 * B);    // 8192
    int K = 5;

    build_kernel<<<dim3(B, 3), BTPB>>>(obj_pts, obj_normals, init_verts,
                                       init_anchors, cg, anchor_verts,
                                       B, V, O, G);

    int warps = B * V;
    int qBlocks = (warps * 32 + QTPB - 1) / QTPB;
    query_kernel<<<qBlocks, QTPB>>>(verts, obj_normals, B, V, O, G);

    int rb = (B * V + 255) / 256;
    final_kernel<<<rb, 256>>>(B, V, G);
    out_kernel<<<1, 1>>>((float*)d_out, B, V, K, out_size);
}